// round 7
// baseline (speedup 1.0000x reference)
#include <cuda_runtime.h>
#include <cstdint>

// ---------------- problem constants ----------------
static constexpr int E_  = 8;
static constexpr int H_  = 1024;
static constexpr int F_  = 4096;
static constexpr int T_  = 16384;
static constexpr int TPE_ = T_ / E_;   // 2048 tokens per expert

// ---------------- GEMM tile config ----------------
static constexpr int MT = 128;     // M tile
static constexpr int NT = 128;     // N tile
static constexpr int KC = 128;     // K chunk in int8 elements (= bytes) -> 128B SW128 row
static constexpr int A_BYTES = MT * 128;          // 16384 per (hi|lo)
static constexpr int B_BYTES = NT * 128;
static constexpr int OFF_AH = 0;
static constexpr int OFF_AL = A_BYTES;
static constexpr int OFF_BH = 2 * A_BYTES;
static constexpr int OFF_BL = 2 * A_BYTES + B_BYTES;
static constexpr int STAGE_BYTES = 2 * A_BYTES + 2 * B_BYTES;     // 65536
static constexpr int NSTAGE = 3;
static constexpr int SMEM_TOTAL = NSTAGE * STAGE_BYTES;           // 196608
static constexpr int NTHREADS = 256;   // 8 warps

static constexpr float QMAX = 16256.0f;   // 127*128 + 64 headroom -> |q| <= 16256
static constexpr float SI   = 2032.0f;    // fixed intermediate scale = 16256/8  (|inter| <= 8, ~12 sigma)

// ---------------- scratch (static device globals; no allocation) ----------------
__device__ signed char g_x1[(size_t)T_ * H_];
__device__ signed char g_x0[(size_t)T_ * H_];
__device__ signed char g_w1h[(size_t)E_ * F_ * H_];   // transposed: [E][F][H]
__device__ signed char g_w1l[(size_t)E_ * F_ * H_];
__device__ signed char g_w2h[(size_t)E_ * H_ * F_];   // transposed: [E][H][F]
__device__ signed char g_w2l[(size_t)E_ * H_ * F_];
__device__ signed char g_i1[(size_t)T_ * F_];         // quantized gelu(intermediate) hi
__device__ signed char g_i0[(size_t)T_ * F_];         // lo
__device__ int g_maxbits[4];                          // abs-max bits: 0=x, 1=w1, 2=w2

#define DI __device__ __forceinline__

DI uint32_t smem_u32(const void* p) {
    uint32_t a;
    asm("{ .reg .u64 t; cvta.to.shared.u64 t, %1; cvt.u32.u64 %0, t; }"
        : "=r"(a) : "l"(p));
    return a;
}

DI float gelu_tanh(float x) {  // jax.nn.gelu default (approximate=True)
    float x3 = x * x * x;
    float t = tanhf(0.7978845608028654f * (x + 0.044715f * x3));
    return 0.5f * x * (1.0f + t);
}

DI float scale_from_slot(int slot) {   // identical formula everywhere -> bitwise-consistent
    return QMAX / __int_as_float(g_maxbits[slot]);
}

// q in [-16256,16256] -> hi in [-127,127], lo in [-64,64]
DI void quant_pair(float q, signed char& hi, signed char& lo) {
    float f1 = rintf(q * (1.0f / 128.0f));
    float f0 = rintf(q - 128.0f * f1);
    hi = (signed char)(int)f1;
    lo = (signed char)(int)f0;
}

// =================== base-ISA tensor helpers ===================
#define LDSM_X4(r, addr)                                                           \
    asm volatile("ldmatrix.sync.aligned.m8n8.x4.shared.b16 {%0, %1, %2, %3}, [%4];" \
        : "=r"((r)[0]), "=r"((r)[1]), "=r"((r)[2]), "=r"((r)[3]) : "r"(addr))

DI void mma16832(int* c, const uint32_t* a, const uint32_t* b) {
    asm volatile(
        "mma.sync.aligned.m16n8k32.row.col.s32.s8.s8.s32 "
        "{%0, %1, %2, %3}, {%4, %5, %6, %7}, {%8, %9}, {%0, %1, %2, %3};"
        : "+r"(c[0]), "+r"(c[1]), "+r"(c[2]), "+r"(c[3])
        : "r"(a[0]), "r"(a[1]), "r"(a[2]), "r"(a[3]), "r"(b[0]), "r"(b[1]));
}

DI void cpasync16(uint32_t saddr, const void* gptr) {
    asm volatile("cp.async.cg.shared.global [%0], [%1], 16;"
                 :: "r"(saddr), "l"(gptr) : "memory");
}
#define CP_COMMIT() asm volatile("cp.async.commit_group;" ::: "memory")
#define CP_WAIT1()  asm volatile("cp.async.wait_group 1;" ::: "memory")

// async stage loader: A(hi,lo) 128x128B + B(hi,lo) 128x128B, SW128-swizzled
DI void load_stage_async(uint32_t stg_u,
                         const signed char* __restrict__ Ah, const signed char* __restrict__ Al,
                         const signed char* __restrict__ Bh, const signed char* __restrict__ Bl,
                         size_t arow0, size_t brow0, int K, size_t kb, int tid) {
#pragma unroll
    for (int v = tid; v < MT * 8; v += NTHREADS) {
        int r = v >> 3, cc = v & 7;
        size_t gb = (arow0 + r) * (size_t)K + kb + (size_t)cc * 16;
        uint32_t so = (uint32_t)(r * 128 + cc * 16);
        so ^= (so >> 3) & 0x70;
        cpasync16(stg_u + OFF_AH + so, Ah + gb);
        cpasync16(stg_u + OFF_AL + so, Al + gb);
    }
#pragma unroll
    for (int v = tid; v < NT * 8; v += NTHREADS) {
        int r = v >> 3, cc = v & 7;
        size_t gb = (brow0 + r) * (size_t)K + kb + (size_t)cc * 16;
        uint32_t so = (uint32_t)(r * 128 + cc * 16);
        so ^= (so >> 3) & 0x70;
        cpasync16(stg_u + OFF_BH + so, Bh + gb);
        cpasync16(stg_u + OFF_BL + so, Bl + gb);
    }
}

// ---------------- prep kernels ----------------
__global__ void k_init_scales() {
    if (threadIdx.x < 4) g_maxbits[threadIdx.x] = 0;
}

__global__ void k_absmax(const float* __restrict__ p, size_t n, int slot) {
    float m = 0.0f;
    for (size_t i = (size_t)blockIdx.x * blockDim.x + threadIdx.x; i < n;
         i += (size_t)gridDim.x * blockDim.x)
        m = fmaxf(m, fabsf(p[i]));
#pragma unroll
    for (int o = 16; o; o >>= 1)
        m = fmaxf(m, __shfl_xor_sync(0xFFFFFFFFu, m, o));
    if ((threadIdx.x & 31) == 0)
        atomicMax(&g_maxbits[slot], __float_as_int(m));  // positive floats: int order == float order
}

// elementwise fp32 -> int8 hi/lo (x), vectorized x4
__global__ void k_quant(const float4* __restrict__ in,
                        char4* __restrict__ o1, char4* __restrict__ o0,
                        int n4, int slot) {
    int i = blockIdx.x * blockDim.x + threadIdx.x;
    if (i >= n4) return;
    float S = scale_from_slot(slot);
    float4 v = in[i];
    char4 a, b;
    quant_pair(v.x * S, a.x, b.x);
    quant_pair(v.y * S, a.y, b.y);
    quant_pair(v.z * S, a.z, b.z);
    quant_pair(v.w * S, a.w, b.w);
    o1[i] = a; o0[i] = b;
}

// per-expert transpose [R,C] -> [C,R] with int8 hi/lo quantization
__global__ void k_quant_transpose(const float* __restrict__ in,
                                  signed char* __restrict__ o1, signed char* __restrict__ o0,
                                  int R, int C, int slot) {
    __shared__ float tile[32][33];
    float S = scale_from_slot(slot);
    size_t base = (size_t)blockIdx.z * R * C;
    int r0 = blockIdx.y * 32, c0 = blockIdx.x * 32;
    int tx = threadIdx.x, ty = threadIdx.y;
#pragma unroll
    for (int i = ty; i < 32; i += 8)
        tile[i][tx] = in[base + (size_t)(r0 + i) * C + c0 + tx];
    __syncthreads();
#pragma unroll
    for (int i = ty; i < 32; i += 8) {
        float v = tile[tx][i];
        size_t o = base + (size_t)(c0 + i) * R + r0 + tx;
        signed char h, l;
        quant_pair(v * S, h, l);
        o1[o] = h; o0[o] = l;
    }
}

// ---------------- grouped split-int8 IMMA GEMM ----------------
// D_tile = [16384*(X1W1) + 128*(X1W0 + X0W1)] / (Sa*Sb)   (X0W0 dropped, ~2.5e-4)
// A: [E*rowsA_pe, K] K-major int8 hi/lo.  B: [E*rowsB_pe, K] K-major int8 hi/lo.
// GELU_SPLIT: gelu + re-quantize to int8 hi/lo (GEMM1); else fp32 out (GEMM2).
// slotA < 0 means fixed SI scale for A.
template <bool GELU_SPLIT>
__global__ void __launch_bounds__(NTHREADS, 1)
k_gemm(const signed char* __restrict__ Ah, const signed char* __restrict__ Al,
       const signed char* __restrict__ Bh, const signed char* __restrict__ Bl,
       int K, int rowsA_pe, int rowsB_pe,
       signed char* __restrict__ O1, signed char* __restrict__ O0,
       float* __restrict__ Of, int ldo, int slotA, int slotB) {
    extern __shared__ char smem[];
    uint32_t sb = smem_u32(smem);
    int tid = threadIdx.x, wid = tid >> 5, lid = tid & 31;

    size_t arow0 = (size_t)blockIdx.z * rowsA_pe + (size_t)blockIdx.y * MT;
    size_t brow0 = (size_t)blockIdx.z * rowsB_pe + (size_t)blockIdx.x * NT;
    size_t ncol0 = (size_t)blockIdx.x * NT;
    const int NC = K / KC;

    float Sa = (slotA >= 0) ? scale_from_slot(slotA) : SI;
    float Sb = scale_from_slot(slotB);
    float inv = 1.0f / (Sa * Sb);

    // 8 warps: warp grid 2(M) x 4(N); warp tile 64x32 (mt 0..3 m16, nt 0..3 n8)
    int m_off = (wid & 1) * 64;
    int n_off = (wid >> 1) * 32;
    uint32_t xorv = (uint32_t)(lid & 7) << 4;            // SW128 per-row XOR (row bits 0-2)
    uint32_t a_row = (lid & 7) + ((lid >> 3) & 1) * 8;   // ldmatrix row-provider mapping
    uint32_t a_kx  = (uint32_t)(lid >> 4) * 16;          // k-byte half (0/16)
    uint32_t b_row = (lid & 7) + ((lid >> 4) & 1) * 8;
    uint32_t b_kx  = ((uint32_t)(lid >> 3) & 1) * 16;

    int hh[4][4][4], mid[4][4][4];
#pragma unroll
    for (int mt = 0; mt < 4; ++mt)
#pragma unroll
        for (int nt = 0; nt < 4; ++nt)
#pragma unroll
            for (int r = 0; r < 4; ++r) { hh[mt][nt][r] = 0; mid[mt][nt][r] = 0; }

    // prologue: stages 0 and 1 in flight
    load_stage_async(sb, Ah, Al, Bh, Bl, arow0, brow0, K, 0, tid);
    CP_COMMIT();
    if (NC > 1) load_stage_async(sb + STAGE_BYTES, Ah, Al, Bh, Bl, arow0, brow0, K, KC, tid);
    CP_COMMIT();

    for (int c = 0; c < NC; ++c) {
        CP_WAIT1();          // stage c resident
        __syncthreads();     // all warps done with stage c-1 -> buffer reusable
        if (c + 2 < NC)
            load_stage_async(sb + ((c + 2) % NSTAGE) * STAGE_BYTES,
                             Ah, Al, Bh, Bl, arow0, brow0, K, (size_t)(c + 2) * KC, tid);
        CP_COMMIT();         // commit every iter to keep group count stable

        uint32_t stg_u = sb + (c % NSTAGE) * STAGE_BYTES;
#pragma unroll
        for (int ks = 0; ks < KC / 32; ++ks) {   // 4 k32 steps per chunk
            uint32_t ah[4][4], al[4][4], bh[4][2], bl[4][2];
#pragma unroll
            for (int mt = 0; mt < 4; ++mt) {
                uint32_t r = m_off + mt * 16 + a_row;
                uint32_t addr = stg_u + (r << 7) + (((uint32_t)ks * 32 + a_kx) ^ xorv);
                LDSM_X4(ah[mt], addr + OFF_AH);
                LDSM_X4(al[mt], addr + OFF_AL);
            }
#pragma unroll
            for (int np = 0; np < 2; ++np) {
                uint32_t r = n_off + np * 16 + b_row;
                uint32_t addr = stg_u + (r << 7) + (((uint32_t)ks * 32 + b_kx) ^ xorv);
                uint32_t t0[4], t1[4];
                LDSM_X4(t0, addr + OFF_BH);
                LDSM_X4(t1, addr + OFF_BL);
                bh[np * 2][0] = t0[0]; bh[np * 2][1] = t0[1];
                bh[np * 2 + 1][0] = t0[2]; bh[np * 2 + 1][1] = t0[3];
                bl[np * 2][0] = t1[0]; bl[np * 2][1] = t1[1];
                bl[np * 2 + 1][0] = t1[2]; bl[np * 2 + 1][1] = t1[3];
            }
            // product-major: same-acc dependents 16 instructions apart
#pragma unroll
            for (int mt = 0; mt < 4; ++mt)
#pragma unroll
                for (int nt = 0; nt < 4; ++nt)
                    mma16832(hh[mt][nt], ah[mt], bh[nt]);    // X1*W1
#pragma unroll
            for (int mt = 0; mt < 4; ++mt)
#pragma unroll
                for (int nt = 0; nt < 4; ++nt)
                    mma16832(mid[mt][nt], ah[mt], bl[nt]);   // X1*W0
#pragma unroll
            for (int mt = 0; mt < 4; ++mt)
#pragma unroll
                for (int nt = 0; nt < 4; ++nt)
                    mma16832(mid[mt][nt], al[mt], bh[nt]);   // X0*W1
        }
    }

    // epilogue: thread holds D[g][2t..2t+1] (c0,c1) and D[g+8][..] (c2,c3)
    int g = lid >> 2, t2 = (lid & 3) * 2;
#pragma unroll
    for (int mt = 0; mt < 4; ++mt) {
#pragma unroll
        for (int nt = 0; nt < 4; ++nt) {
            size_t col = ncol0 + n_off + nt * 8 + t2;
            size_t row0 = arow0 + m_off + mt * 16 + g;
            size_t row1 = row0 + 8;
            float v0 = fmaf(16384.0f, (float)hh[mt][nt][0], 128.0f * (float)mid[mt][nt][0]) * inv;
            float v1 = fmaf(16384.0f, (float)hh[mt][nt][1], 128.0f * (float)mid[mt][nt][1]) * inv;
            float v2 = fmaf(16384.0f, (float)hh[mt][nt][2], 128.0f * (float)mid[mt][nt][2]) * inv;
            float v3 = fmaf(16384.0f, (float)hh[mt][nt][3], 128.0f * (float)mid[mt][nt][3]) * inv;
            if (GELU_SPLIT) {
                float q0 = fminf(fmaxf(gelu_tanh(v0) * SI, -QMAX), QMAX);
                float q1 = fminf(fmaxf(gelu_tanh(v1) * SI, -QMAX), QMAX);
                float q2 = fminf(fmaxf(gelu_tanh(v2) * SI, -QMAX), QMAX);
                float q3 = fminf(fmaxf(gelu_tanh(v3) * SI, -QMAX), QMAX);
                char2 h0, l0, h1, l1;
                quant_pair(q0, h0.x, l0.x); quant_pair(q1, h0.y, l0.y);
                quant_pair(q2, h1.x, l1.x); quant_pair(q3, h1.y, l1.y);
                *(char2*)(O1 + row0 * (size_t)ldo + col) = h0;
                *(char2*)(O0 + row0 * (size_t)ldo + col) = l0;
                *(char2*)(O1 + row1 * (size_t)ldo + col) = h1;
                *(char2*)(O0 + row1 * (size_t)ldo + col) = l1;
            } else {
                *(float2*)(Of + row0 * (size_t)ldo + col) = make_float2(v0, v1);
                *(float2*)(Of + row1 * (size_t)ldo + col) = make_float2(v2, v3);
            }
        }
    }
}

// ---------------- launch ----------------
extern "C" void kernel_launch(void* const* d_in, const int* in_sizes, int n_in,
                              void* d_out, int out_size) {
    (void)in_sizes; (void)n_in; (void)out_size;
    const float* x  = (const float*)d_in[0];
    const float* w1 = (const float*)d_in[1];   // [E, H, F]
    const float* w2 = (const float*)d_in[2];   // [E, F, H]
    float* out = (float*)d_out;                // [T, H]

    signed char *x1, *x0, *w1h, *w1l, *w2h, *w2l, *i1, *i0;
    cudaGetSymbolAddress((void**)&x1,  g_x1);
    cudaGetSymbolAddress((void**)&x0,  g_x0);
    cudaGetSymbolAddress((void**)&w1h, g_w1h);
    cudaGetSymbolAddress((void**)&w1l, g_w1l);
    cudaGetSymbolAddress((void**)&w2h, g_w2h);
    cudaGetSymbolAddress((void**)&w2l, g_w2l);
    cudaGetSymbolAddress((void**)&i1,  g_i1);
    cudaGetSymbolAddress((void**)&i0,  g_i0);

    // scales (deterministic device-side abs-max)
    k_init_scales<<<1, 32>>>();
    k_absmax<<<1024, 256>>>(x,  (size_t)T_ * H_,      0);
    k_absmax<<<1024, 256>>>(w1, (size_t)E_ * H_ * F_, 1);
    k_absmax<<<1024, 256>>>(w2, (size_t)E_ * F_ * H_, 2);

    // quantize x; transpose+quantize weights to K-major B operands
    int n4 = T_ * H_ / 4;
    k_quant<<<(n4 + 255) / 256, 256>>>((const float4*)x, (char4*)x1, (char4*)x0, n4, 0);
    dim3 tb(32, 8);
    k_quant_transpose<<<dim3(F_ / 32, H_ / 32, E_), tb>>>(w1, w1h, w1l, H_, F_, 1); // -> [E,F,H]
    k_quant_transpose<<<dim3(H_ / 32, F_ / 32, E_), tb>>>(w2, w2h, w2l, F_, H_, 2); // -> [E,H,F]

    cudaFuncSetAttribute(k_gemm<true>,  cudaFuncAttributeMaxDynamicSharedMemorySize, SMEM_TOTAL);
    cudaFuncSetAttribute(k_gemm<false>, cudaFuncAttributeMaxDynamicSharedMemorySize, SMEM_TOTAL);

    // GEMM1: I = gelu(X @ W1) -> int8 hi/lo, [T, F]
    k_gemm<true><<<dim3(F_ / NT, TPE_ / MT, E_), NTHREADS, SMEM_TOTAL>>>(
        x1, x0, w1h, w1l, H_, TPE_, F_, i1, i0, nullptr, F_, 0, 1);
    // GEMM2: out = I @ W2 -> fp32, [T, H]
    k_gemm<false><<<dim3(H_ / NT, TPE_ / MT, E_), NTHREADS, SMEM_TOTAL>>>(
        i1, i0, w2h, w2l, F_, TPE_, H_, nullptr, nullptr, out, H_, -1, 2);
}

// round 8
// speedup vs baseline: 5.9210x; 5.9210x over previous
#include <cuda_runtime.h>
#include <cuda_fp16.h>
#include <cstdint>

// ---------------- problem constants ----------------
static constexpr int E_  = 8;
static constexpr int H_  = 1024;
static constexpr int F_  = 4096;
static constexpr int T_  = 16384;
static constexpr int TPE_ = T_ / E_;   // 2048 tokens per expert

// ---------------- GEMM tile config ----------------
static constexpr int MT = 128;     // M tile
static constexpr int NT = 128;     // N tile
static constexpr int KC = 64;      // K chunk (fp16 elements) = 128B SW128 row
static constexpr int A_BYTES = MT * 128;          // 16384
static constexpr int B_BYTES = NT * 128;          // 16384
static constexpr int OFF_A = 0;
static constexpr int OFF_B = A_BYTES;
static constexpr int STAGE_BYTES = A_BYTES + B_BYTES;   // 32768
static constexpr int NSTAGE = 3;
static constexpr int SMEM_TOTAL = NSTAGE * STAGE_BYTES; // 98304
static constexpr int NTHREADS = 256;   // 8 warps

// ---------------- scratch (static device globals; no allocation) ----------------
__device__ __half g_xq[(size_t)T_ * H_];
__device__ __half g_w1q[(size_t)E_ * F_ * H_];   // transposed: [E][F][H]
__device__ __half g_w2q[(size_t)E_ * H_ * F_];   // transposed: [E][H][F]
__device__ __half g_iq[(size_t)T_ * F_];         // gelu(intermediate), fp16

#define DI __device__ __forceinline__

DI uint32_t smem_u32(const void* p) {
    uint32_t a;
    asm("{ .reg .u64 t; cvta.to.shared.u64 t, %1; cvt.u32.u64 %0, t; }"
        : "=r"(a) : "l"(p));
    return a;
}

DI float gelu_tanh(float x) {  // jax.nn.gelu default (approximate=True)
    float x3 = x * x * x;
    float t = tanhf(0.7978845608028654f * (x + 0.044715f * x3));
    return 0.5f * x * (1.0f + t);
}

// =================== tensor helpers (base ISA) ===================
#define LDSM_X4(r, addr)                                                           \
    asm volatile("ldmatrix.sync.aligned.m8n8.x4.shared.b16 {%0, %1, %2, %3}, [%4];" \
        : "=r"((r)[0]), "=r"((r)[1]), "=r"((r)[2]), "=r"((r)[3]) : "r"(addr))

DI void mma16816(float* c, const uint32_t* a, const uint32_t* b) {
    asm volatile(
        "mma.sync.aligned.m16n8k16.row.col.f32.f16.f16.f32 "
        "{%0, %1, %2, %3}, {%4, %5, %6, %7}, {%8, %9}, {%0, %1, %2, %3};"
        : "+f"(c[0]), "+f"(c[1]), "+f"(c[2]), "+f"(c[3])
        : "r"(a[0]), "r"(a[1]), "r"(a[2]), "r"(a[3]), "r"(b[0]), "r"(b[1]));
}

DI void cpasync16(uint32_t saddr, const void* gptr) {
    asm volatile("cp.async.cg.shared.global [%0], [%1], 16;"
                 :: "r"(saddr), "l"(gptr) : "memory");
}
#define CP_COMMIT() asm volatile("cp.async.commit_group;" ::: "memory")
#define CP_WAIT1()  asm volatile("cp.async.wait_group 1;" ::: "memory")

// async stage loader: A 128x128B + B 128x128B, SW128-swizzled
DI void load_stage_async(uint32_t stg_u,
                         const __half* __restrict__ A, const __half* __restrict__ B,
                         size_t arow0, size_t brow0, int K, size_t kb, int tid) {
#pragma unroll
    for (int v = tid; v < MT * 8; v += NTHREADS) {
        int r = v >> 3, cc = v & 7;
        size_t gb = ((arow0 + r) * (size_t)K + kb) * 2 + (size_t)cc * 16;
        uint32_t so = (uint32_t)(r * 128 + cc * 16);
        so ^= (so >> 3) & 0x70;
        cpasync16(stg_u + OFF_A + so, (const char*)A + gb);
    }
#pragma unroll
    for (int v = tid; v < NT * 8; v += NTHREADS) {
        int r = v >> 3, cc = v & 7;
        size_t gb = ((brow0 + r) * (size_t)K + kb) * 2 + (size_t)cc * 16;
        uint32_t so = (uint32_t)(r * 128 + cc * 16);
        so ^= (so >> 3) & 0x70;
        cpasync16(stg_u + OFF_B + so, (const char*)B + gb);
    }
}

// ---------------- prep kernels ----------------
// fp32 -> fp16 elementwise, vectorized x4
__global__ void k_cvt(const float4* __restrict__ in, __half2* __restrict__ o, int n4) {
    int i = blockIdx.x * blockDim.x + threadIdx.x;
    if (i >= n4) return;
    float4 v = in[i];
    o[2 * i]     = __floats2half2_rn(v.x, v.y);
    o[2 * i + 1] = __floats2half2_rn(v.z, v.w);
}

// per-expert transpose [R,C] -> [C,R] with fp32->fp16 conversion
__global__ void k_transpose_cvt(const float* __restrict__ in, __half* __restrict__ o,
                                int R, int C) {
    __shared__ float tile[32][33];
    size_t base = (size_t)blockIdx.z * R * C;
    int r0 = blockIdx.y * 32, c0 = blockIdx.x * 32;
    int tx = threadIdx.x, ty = threadIdx.y;
#pragma unroll
    for (int i = ty; i < 32; i += 8)
        tile[i][tx] = in[base + (size_t)(r0 + i) * C + c0 + tx];
    __syncthreads();
#pragma unroll
    for (int i = ty; i < 32; i += 8) {
        float v = tile[tx][i];
        size_t oo = base + (size_t)(c0 + i) * R + r0 + tx;
        o[oo] = __float2half_rn(v);
    }
}

// ---------------- grouped fp16 GEMM (single product, fp32 accum) ----------------
// A: [E*rowsA_pe, K] K-major fp16.  B: [E*rowsB_pe, K] K-major fp16.
// GELU_SPLIT: apply tanh-gelu, emit fp16 (GEMM1); else emit fp32 (GEMM2).
template <bool GELU_SPLIT>
__global__ void __launch_bounds__(NTHREADS, 1)
k_gemm(const __half* __restrict__ A, const __half* __restrict__ B,
       int K, int rowsA_pe, int rowsB_pe,
       __half* __restrict__ Oh, float* __restrict__ Of, int ldo) {
    extern __shared__ char smem[];
    uint32_t sb = smem_u32(smem);
    int tid = threadIdx.x, wid = tid >> 5, lid = tid & 31;

    size_t arow0 = (size_t)blockIdx.z * rowsA_pe + (size_t)blockIdx.y * MT;
    size_t brow0 = (size_t)blockIdx.z * rowsB_pe + (size_t)blockIdx.x * NT;
    size_t ncol0 = (size_t)blockIdx.x * NT;
    const int NC = K / KC;

    // 8 warps: warp grid 2(M) x 4(N); warp tile 64x32 (mt 0..3 m16, nt 0..3 n8)
    int m_off = (wid & 1) * 64;
    int n_off = (wid >> 1) * 32;
    uint32_t xorv = (uint32_t)(lid & 7) << 4;            // SW128 per-row XOR
    uint32_t a_row = (lid & 7) + ((lid >> 3) & 1) * 8;   // ldmatrix row-provider map
    uint32_t a_kx  = (uint32_t)(lid >> 4) * 16;          // k-byte half (0/16)
    uint32_t b_row = (lid & 7) + ((lid >> 4) & 1) * 8;
    uint32_t b_kx  = ((uint32_t)(lid >> 3) & 1) * 16;

    float acc[4][4][4];
#pragma unroll
    for (int mt = 0; mt < 4; ++mt)
#pragma unroll
        for (int nt = 0; nt < 4; ++nt)
#pragma unroll
            for (int r = 0; r < 4; ++r) acc[mt][nt][r] = 0.0f;

    // prologue: stages 0 and 1 in flight
    load_stage_async(sb, A, B, arow0, brow0, K, 0, tid);
    CP_COMMIT();
    if (NC > 1) load_stage_async(sb + STAGE_BYTES, A, B, arow0, brow0, K, KC, tid);
    CP_COMMIT();

    for (int c = 0; c < NC; ++c) {
        CP_WAIT1();          // stage c resident
        __syncthreads();     // all warps done with stage c-1 -> buffer reusable
        if (c + 2 < NC)
            load_stage_async(sb + ((c + 2) % NSTAGE) * STAGE_BYTES,
                             A, B, arow0, brow0, K, (size_t)(c + 2) * KC, tid);
        CP_COMMIT();         // commit every iter to keep group count stable

        uint32_t stg_u = sb + (c % NSTAGE) * STAGE_BYTES;
#pragma unroll
        for (int ks = 0; ks < KC / 16; ++ks) {
            uint32_t av[4][4], bv[4][2];
#pragma unroll
            for (int mt = 0; mt < 4; ++mt) {
                uint32_t r = m_off + mt * 16 + a_row;
                uint32_t addr = stg_u + OFF_A + (r << 7) + (((uint32_t)ks * 32 + a_kx) ^ xorv);
                LDSM_X4(av[mt], addr);
            }
#pragma unroll
            for (int np = 0; np < 2; ++np) {
                uint32_t r = n_off + np * 16 + b_row;
                uint32_t addr = stg_u + OFF_B + (r << 7) + (((uint32_t)ks * 32 + b_kx) ^ xorv);
                uint32_t t0[4];
                LDSM_X4(t0, addr);
                bv[np * 2][0] = t0[0]; bv[np * 2][1] = t0[1];
                bv[np * 2 + 1][0] = t0[2]; bv[np * 2 + 1][1] = t0[3];
            }
#pragma unroll
            for (int mt = 0; mt < 4; ++mt)
#pragma unroll
                for (int nt = 0; nt < 4; ++nt)
                    mma16816(acc[mt][nt], av[mt], bv[nt]);
        }
    }

    // epilogue: thread holds D[g][2t..2t+1] (c0,c1) and D[g+8][2t..2t+1] (c2,c3)
    int g = lid >> 2, t2 = (lid & 3) * 2;
#pragma unroll
    for (int mt = 0; mt < 4; ++mt) {
#pragma unroll
        for (int nt = 0; nt < 4; ++nt) {
            size_t col = ncol0 + n_off + nt * 8 + t2;
            size_t row0 = arow0 + m_off + mt * 16 + g;
            size_t row1 = row0 + 8;
            float c0 = acc[mt][nt][0], c1 = acc[mt][nt][1];
            float c2 = acc[mt][nt][2], c3 = acc[mt][nt][3];
            if (GELU_SPLIT) {
                __half2 p0 = __floats2half2_rn(gelu_tanh(c0), gelu_tanh(c1));
                __half2 p1 = __floats2half2_rn(gelu_tanh(c2), gelu_tanh(c3));
                *(__half2*)(Oh + row0 * (size_t)ldo + col) = p0;
                *(__half2*)(Oh + row1 * (size_t)ldo + col) = p1;
            } else {
                *(float2*)(Of + row0 * (size_t)ldo + col) = make_float2(c0, c1);
                *(float2*)(Of + row1 * (size_t)ldo + col) = make_float2(c2, c3);
            }
        }
    }
}

// ---------------- launch ----------------
extern "C" void kernel_launch(void* const* d_in, const int* in_sizes, int n_in,
                              void* d_out, int out_size) {
    (void)in_sizes; (void)n_in; (void)out_size;
    const float* x  = (const float*)d_in[0];
    const float* w1 = (const float*)d_in[1];   // [E, H, F]
    const float* w2 = (const float*)d_in[2];   // [E, F, H]
    float* out = (float*)d_out;                // [T, H]

    __half *xq, *w1q, *w2q, *iq;
    cudaGetSymbolAddress((void**)&xq,  g_xq);
    cudaGetSymbolAddress((void**)&w1q, g_w1q);
    cudaGetSymbolAddress((void**)&w2q, g_w2q);
    cudaGetSymbolAddress((void**)&iq,  g_iq);

    // prep: convert x; transpose+convert weights to K-major B operands
    int n4 = T_ * H_ / 4;
    k_cvt<<<(n4 + 255) / 256, 256>>>((const float4*)x, (__half2*)xq, n4);
    dim3 tb(32, 8);
    k_transpose_cvt<<<dim3(F_ / 32, H_ / 32, E_), tb>>>(w1, w1q, H_, F_); // -> [E,F,H]
    k_transpose_cvt<<<dim3(H_ / 32, F_ / 32, E_), tb>>>(w2, w2q, F_, H_); // -> [E,H,F]

    cudaFuncSetAttribute(k_gemm<true>,  cudaFuncAttributeMaxDynamicSharedMemorySize, SMEM_TOTAL);
    cudaFuncSetAttribute(k_gemm<false>, cudaFuncAttributeMaxDynamicSharedMemorySize, SMEM_TOTAL);

    // GEMM1: I = gelu(X @ W1) -> fp16, [T, F]
    k_gemm<true><<<dim3(F_ / NT, TPE_ / MT, E_), NTHREADS, SMEM_TOTAL>>>(
        xq, w1q, H_, TPE_, F_, iq, nullptr, F_);
    // GEMM2: out = I @ W2 -> fp32, [T, H]
    k_gemm<false><<<dim3(H_ / NT, TPE_ / MT, E_), NTHREADS, SMEM_TOTAL>>>(
        iq, w2q, F_, TPE_, H_, nullptr, out, H_);
}

// round 10
// speedup vs baseline: 6.2536x; 1.0562x over previous
#include <cuda_runtime.h>
#include <cuda_fp16.h>
#include <cstdint>

// ---------------- problem constants ----------------
static constexpr int E_  = 8;
static constexpr int H_  = 1024;
static constexpr int F_  = 4096;
static constexpr int T_  = 16384;
static constexpr int TPE_ = T_ / E_;   // 2048 tokens per expert

// ---------------- GEMM tile config ----------------
static constexpr int MT = 128;     // M tile
static constexpr int NT = 128;     // N tile
static constexpr int KC = 128;     // K chunk (fp16 elements) = 2 x 128B SW128 row-blocks
static constexpr int BLK = 16384;  // one 128-row x 128B block
static constexpr int OFF_A = 0;            // A: block0, block1
static constexpr int OFF_B = 2 * BLK;      // B: block0, block1
static constexpr int STAGE_BYTES = 4 * BLK;             // 65536
static constexpr int NSTAGE = 3;
static constexpr int SMEM_TOTAL = NSTAGE * STAGE_BYTES; // 196608
static constexpr int NTHREADS = 512;   // 16 warps

// ---------------- scratch (static device globals; no allocation) ----------------
__device__ __half g_xq[(size_t)T_ * H_];
__device__ __half g_w1q[(size_t)E_ * F_ * H_];   // transposed: [E][F][H]
__device__ __half g_w2q[(size_t)E_ * H_ * F_];   // transposed: [E][H][F]
__device__ __half g_iq[(size_t)T_ * F_];         // gelu(intermediate), fp16

#define DI __device__ __forceinline__

DI uint32_t smem_u32(const void* p) {
    uint32_t a;
    asm("{ .reg .u64 t; cvta.to.shared.u64 t, %1; cvt.u32.u64 %0, t; }"
        : "=r"(a) : "l"(p));
    return a;
}

DI float gelu_tanh(float x) {  // jax.nn.gelu default (approximate=True)
    float x3 = x * x * x;
    float t = tanhf(0.7978845608028654f * (x + 0.044715f * x3));
    return 0.5f * x * (1.0f + t);
}

// =================== tensor helpers (base ISA) ===================
#define LDSM_X4(r, addr)                                                           \
    asm volatile("ldmatrix.sync.aligned.m8n8.x4.shared.b16 {%0, %1, %2, %3}, [%4];" \
        : "=r"((r)[0]), "=r"((r)[1]), "=r"((r)[2]), "=r"((r)[3]) : "r"(addr))

DI void mma16816(float* c, const uint32_t* a, const uint32_t* b) {
    asm volatile(
        "mma.sync.aligned.m16n8k16.row.col.f32.f16.f16.f32 "
        "{%0, %1, %2, %3}, {%4, %5, %6, %7}, {%8, %9}, {%0, %1, %2, %3};"
        : "+f"(c[0]), "+f"(c[1]), "+f"(c[2]), "+f"(c[3])
        : "r"(a[0]), "r"(a[1]), "r"(a[2]), "r"(a[3]), "r"(b[0]), "r"(b[1]));
}

DI void cpasync16(uint32_t saddr, const void* gptr) {
    asm volatile("cp.async.cg.shared.global [%0], [%1], 16;"
                 :: "r"(saddr), "l"(gptr) : "memory");
}
#define CP_COMMIT() asm volatile("cp.async.commit_group;" ::: "memory")
#define CP_WAIT1()  asm volatile("cp.async.wait_group 1;" ::: "memory")

// async stage loader: A 128x256B + B 128x256B (each as 2 x 128B blocks), SW128-swizzled
DI void load_stage_async(uint32_t stg_u,
                         const __half* __restrict__ A, const __half* __restrict__ B,
                         size_t arow0, size_t brow0, int K, size_t kb, int tid) {
#pragma unroll
    for (int v = tid; v < MT * 16; v += NTHREADS) {
        int r = v >> 4, cc = v & 15;                 // cc: 16B unit within 256B row
        size_t gb = ((arow0 + r) * (size_t)K + kb) * 2 + (size_t)cc * 16;
        int sub = cc >> 3, c8 = cc & 7;
        uint32_t so = (uint32_t)(r * 128 + c8 * 16);
        so ^= (so >> 3) & 0x70;
        cpasync16(stg_u + OFF_A + sub * BLK + so, (const char*)A + gb);
    }
#pragma unroll
    for (int v = tid; v < NT * 16; v += NTHREADS) {
        int r = v >> 4, cc = v & 15;
        size_t gb = ((brow0 + r) * (size_t)K + kb) * 2 + (size_t)cc * 16;
        int sub = cc >> 3, c8 = cc & 7;
        uint32_t so = (uint32_t)(r * 128 + c8 * 16);
        so ^= (so >> 3) & 0x70;
        cpasync16(stg_u + OFF_B + sub * BLK + so, (const char*)B + gb);
    }
}

// ---------------- prep kernels ----------------
// fp32 -> fp16 elementwise, vectorized x4
__global__ void k_cvt(const float4* __restrict__ in, __half2* __restrict__ o, int n4) {
    int i = blockIdx.x * blockDim.x + threadIdx.x;
    if (i >= n4) return;
    float4 v = in[i];
    o[2 * i]     = __floats2half2_rn(v.x, v.y);
    o[2 * i + 1] = __floats2half2_rn(v.z, v.w);
}

// per-expert transpose [R,C] -> [C,R] with fp32->fp16 conversion
__global__ void k_transpose_cvt(const float* __restrict__ in, __half* __restrict__ o,
                                int R, int C) {
    __shared__ float tile[32][33];
    size_t base = (size_t)blockIdx.z * R * C;
    int r0 = blockIdx.y * 32, c0 = blockIdx.x * 32;
    int tx = threadIdx.x, ty = threadIdx.y;
#pragma unroll
    for (int i = ty; i < 32; i += 8)
        tile[i][tx] = in[base + (size_t)(r0 + i) * C + c0 + tx];
    __syncthreads();
#pragma unroll
    for (int i = ty; i < 32; i += 8) {
        float v = tile[tx][i];
        size_t oo = base + (size_t)(c0 + i) * R + r0 + tx;
        o[oo] = __float2half_rn(v);
    }
}

// ---------------- grouped fp16 GEMM (single product, fp32 accum) ----------------
// A: [E*rowsA_pe, K] K-major fp16.  B: [E*rowsB_pe, K] K-major fp16.
// GELU_SPLIT: apply tanh-gelu, emit fp16 (GEMM1); else emit fp32 (GEMM2).
template <bool GELU_SPLIT>
__global__ void __launch_bounds__(NTHREADS, 1)
k_gemm(const __half* __restrict__ A, const __half* __restrict__ B,
       int K, int rowsA_pe, int rowsB_pe,
       __half* __restrict__ Oh, float* __restrict__ Of, int ldo) {
    extern __shared__ char smem[];
    uint32_t sb = smem_u32(smem);
    int tid = threadIdx.x, wid = tid >> 5, lid = tid & 31;

    size_t arow0 = (size_t)blockIdx.z * rowsA_pe + (size_t)blockIdx.y * MT;
    size_t brow0 = (size_t)blockIdx.z * rowsB_pe + (size_t)blockIdx.x * NT;
    size_t ncol0 = (size_t)blockIdx.x * NT;
    const int NC = K / KC;

    // 16 warps: warp grid 4(M) x 4(N); warp tile 32x32 (mt 0..1 m16, nt 0..3 n8)
    int m_off = (wid & 3) * 32;
    int n_off = (wid >> 2) * 32;
    uint32_t xorv = (uint32_t)(lid & 7) << 4;            // SW128 per-row XOR
    uint32_t a_row = (lid & 7) + ((lid >> 3) & 1) * 8;   // ldmatrix row-provider map
    uint32_t a_kx  = (uint32_t)(lid >> 4) * 16;          // k-byte half (0/16)
    uint32_t b_row = (lid & 7) + ((lid >> 4) & 1) * 8;
    uint32_t b_kx  = ((uint32_t)(lid >> 3) & 1) * 16;

    float acc[2][4][4];
#pragma unroll
    for (int mt = 0; mt < 2; ++mt)
#pragma unroll
        for (int nt = 0; nt < 4; ++nt)
#pragma unroll
            for (int r = 0; r < 4; ++r) acc[mt][nt][r] = 0.0f;

    // prologue: stages 0 and 1 in flight
    load_stage_async(sb, A, B, arow0, brow0, K, 0, tid);
    CP_COMMIT();
    if (NC > 1) load_stage_async(sb + STAGE_BYTES, A, B, arow0, brow0, K, KC, tid);
    CP_COMMIT();

    for (int c = 0; c < NC; ++c) {
        CP_WAIT1();          // this thread's stage-c cp.asyncs landed
        __syncthreads();     // all threads' stage-c data visible; stage c-1 reusable
        if (c + 2 < NC)
            load_stage_async(sb + ((c + 2) % NSTAGE) * STAGE_BYTES,
                             A, B, arow0, brow0, K, (size_t)(c + 2) * KC, tid);
        CP_COMMIT();         // commit every iter to keep group count stable

        uint32_t stg_u = sb + (c % NSTAGE) * STAGE_BYTES;
#pragma unroll
        for (int ks = 0; ks < KC / 16; ++ks) {           // 8 k16 steps (2 blocks x 4)
            uint32_t blk_off = (uint32_t)(ks >> 2) * BLK;
            uint32_t kin = (uint32_t)(ks & 3) * 32;
            uint32_t av[2][4], bv[4][2];
#pragma unroll
            for (int mt = 0; mt < 2; ++mt) {
                uint32_t r = m_off + mt * 16 + a_row;
                uint32_t addr = stg_u + OFF_A + blk_off + (r << 7) + ((kin + a_kx) ^ xorv);
                LDSM_X4(av[mt], addr);
            }
#pragma unroll
            for (int np = 0; np < 2; ++np) {
                uint32_t r = n_off + np * 16 + b_row;
                uint32_t addr = stg_u + OFF_B + blk_off + (r << 7) + ((kin + b_kx) ^ xorv);
                uint32_t t0[4];
                LDSM_X4(t0, addr);
                bv[np * 2][0] = t0[0]; bv[np * 2][1] = t0[1];
                bv[np * 2 + 1][0] = t0[2]; bv[np * 2 + 1][1] = t0[3];
            }
#pragma unroll
            for (int mt = 0; mt < 2; ++mt)
#pragma unroll
                for (int nt = 0; nt < 4; ++nt)
                    mma16816(acc[mt][nt], av[mt], bv[nt]);
        }
    }

    // epilogue: thread holds D[g][2t..2t+1] (c0,c1) and D[g+8][2t..2t+1] (c2,c3)
    int g = lid >> 2, t2 = (lid & 3) * 2;
#pragma unroll
    for (int mt = 0; mt < 2; ++mt) {
#pragma unroll
        for (int nt = 0; nt < 4; ++nt) {
            size_t col = ncol0 + n_off + nt * 8 + t2;
            size_t row0 = arow0 + m_off + mt * 16 + g;
            size_t row1 = row0 + 8;
            float c0 = acc[mt][nt][0], c1 = acc[mt][nt][1];
            float c2 = acc[mt][nt][2], c3 = acc[mt][nt][3];
            if (GELU_SPLIT) {
                __half2 p0 = __floats2half2_rn(gelu_tanh(c0), gelu_tanh(c1));
                __half2 p1 = __floats2half2_rn(gelu_tanh(c2), gelu_tanh(c3));
                *(__half2*)(Oh + row0 * (size_t)ldo + col) = p0;
                *(__half2*)(Oh + row1 * (size_t)ldo + col) = p1;
            } else {
                *(float2*)(Of + row0 * (size_t)ldo + col) = make_float2(c0, c1);
                *(float2*)(Of + row1 * (size_t)ldo + col) = make_float2(c2, c3);
            }
        }
    }
}

// ---------------- launch ----------------
extern "C" void kernel_launch(void* const* d_in, const int* in_sizes, int n_in,
                              void* d_out, int out_size) {
    (void)in_sizes; (void)n_in; (void)out_size;
    const float* x  = (const float*)d_in[0];
    const float* w1 = (const float*)d_in[1];   // [E, H, F]
    const float* w2 = (const float*)d_in[2];   // [E, F, H]
    float* out = (float*)d_out;                // [T, H]

    __half *xq, *w1q, *w2q, *iq;
    cudaGetSymbolAddress((void**)&xq,  g_xq);
    cudaGetSymbolAddress((void**)&w1q, g_w1q);
    cudaGetSymbolAddress((void**)&w2q, g_w2q);
    cudaGetSymbolAddress((void**)&iq,  g_iq);

    // prep: convert x; transpose+convert weights to K-major B operands
    int n4 = T_ * H_ / 4;
    k_cvt<<<(n4 + 255) / 256, 256>>>((const float4*)x, (__half2*)xq, n4);
    dim3 tb(32, 8);
    k_transpose_cvt<<<dim3(F_ / 32, H_ / 32, E_), tb>>>(w1, w1q, H_, F_); // -> [E,F,H]
    k_transpose_cvt<<<dim3(H_ / 32, F_ / 32, E_), tb>>>(w2, w2q, F_, H_); // -> [E,H,F]

    cudaFuncSetAttribute(k_gemm<true>,  cudaFuncAttributeMaxDynamicSharedMemorySize, SMEM_TOTAL);
    cudaFuncSetAttribute(k_gemm<false>, cudaFuncAttributeMaxDynamicSharedMemorySize, SMEM_TOTAL);

    // GEMM1: I = gelu(X @ W1) -> fp16, [T, F]
    k_gemm<true><<<dim3(F_ / NT, TPE_ / MT, E_), NTHREADS, SMEM_TOTAL>>>(
        xq, w1q, H_, TPE_, F_, iq, nullptr, F_);
    // GEMM2: out = I @ W2 -> fp32, [T, H]
    k_gemm<false><<<dim3(H_ / NT, TPE_ / MT, E_), NTHREADS, SMEM_TOTAL>>>(
        iq, w2q, F_, TPE_, H_, nullptr, out, H_);
}

// round 11
// speedup vs baseline: 6.6196x; 1.0585x over previous
#include <cuda_runtime.h>
#include <cuda_fp16.h>
#include <cstdint>

// ---------------- problem constants ----------------
static constexpr int E_  = 8;
static constexpr int H_  = 1024;
static constexpr int F_  = 4096;
static constexpr int T_  = 16384;
static constexpr int TPE_ = T_ / E_;   // 2048 tokens per expert

// ---------------- GEMM tile config ----------------
static constexpr int MT = 256;     // M tile
static constexpr int NT = 128;     // N tile
static constexpr int KC = 64;      // K chunk (fp16) = one 128B SW128 row-block
static constexpr int A_BYTES = MT * 128;          // 32768
static constexpr int B_BYTES = NT * 128;          // 16384
static constexpr int OFF_A = 0;
static constexpr int OFF_B = A_BYTES;
static constexpr int STAGE_BYTES = A_BYTES + B_BYTES;   // 49152
static constexpr int NSTAGE = 4;
static constexpr int SMEM_TOTAL = NSTAGE * STAGE_BYTES; // 196608
static constexpr int NTHREADS = 512;   // 16 warps

// ---------------- scratch (static device globals; no allocation) ----------------
__device__ __half g_xq[(size_t)T_ * H_];
__device__ __half g_w1q[(size_t)E_ * F_ * H_];   // transposed: [E][F][H]
__device__ __half g_w2q[(size_t)E_ * H_ * F_];   // transposed: [E][H][F]
__device__ __half g_iq[(size_t)T_ * F_];         // gelu(intermediate), fp16

#define DI __device__ __forceinline__

DI uint32_t smem_u32(const void* p) {
    uint32_t a;
    asm("{ .reg .u64 t; cvta.to.shared.u64 t, %1; cvt.u32.u64 %0, t; }"
        : "=r"(a) : "l"(p));
    return a;
}

DI float gelu_tanh(float x) {  // jax.nn.gelu default (approximate=True)
    float x3 = x * x * x;
    float t = tanhf(0.7978845608028654f * (x + 0.044715f * x3));
    return 0.5f * x * (1.0f + t);
}

// =================== tensor helpers (base ISA) ===================
#define LDSM_X4(r, addr)                                                           \
    asm volatile("ldmatrix.sync.aligned.m8n8.x4.shared.b16 {%0, %1, %2, %3}, [%4];" \
        : "=r"((r)[0]), "=r"((r)[1]), "=r"((r)[2]), "=r"((r)[3]) : "r"(addr))

DI void mma16816(float* c, const uint32_t* a, const uint32_t* b) {
    asm volatile(
        "mma.sync.aligned.m16n8k16.row.col.f32.f16.f16.f32 "
        "{%0, %1, %2, %3}, {%4, %5, %6, %7}, {%8, %9}, {%0, %1, %2, %3};"
        : "+f"(c[0]), "+f"(c[1]), "+f"(c[2]), "+f"(c[3])
        : "r"(a[0]), "r"(a[1]), "r"(a[2]), "r"(a[3]), "r"(b[0]), "r"(b[1]));
}

DI void cpasync16(uint32_t saddr, const void* gptr) {
    asm volatile("cp.async.cg.shared.global [%0], [%1], 16;"
                 :: "r"(saddr), "l"(gptr) : "memory");
}
#define CP_COMMIT() asm volatile("cp.async.commit_group;" ::: "memory")
#define CP_WAIT2()  asm volatile("cp.async.wait_group 2;" ::: "memory")

// async stage loader: A 256x128B + B 128x128B, SW128-swizzled
DI void load_stage_async(uint32_t stg_u,
                         const __half* __restrict__ A, const __half* __restrict__ B,
                         size_t arow0, size_t brow0, int K, size_t kb, int tid) {
#pragma unroll
    for (int v = tid; v < MT * 8; v += NTHREADS) {
        int r = v >> 3, cc = v & 7;
        size_t gb = ((arow0 + r) * (size_t)K + kb) * 2 + (size_t)cc * 16;
        uint32_t so = (uint32_t)(r * 128 + cc * 16);
        so ^= (so >> 3) & 0x70;
        cpasync16(stg_u + OFF_A + so, (const char*)A + gb);
    }
#pragma unroll
    for (int v = tid; v < NT * 8; v += NTHREADS) {
        int r = v >> 3, cc = v & 7;
        size_t gb = ((brow0 + r) * (size_t)K + kb) * 2 + (size_t)cc * 16;
        uint32_t so = (uint32_t)(r * 128 + cc * 16);
        so ^= (so >> 3) & 0x70;
        cpasync16(stg_u + OFF_B + so, (const char*)B + gb);
    }
}

// ---------------- prep kernels ----------------
// fp32 -> fp16 elementwise, vectorized x4
__global__ void k_cvt(const float4* __restrict__ in, __half2* __restrict__ o, int n4) {
    int i = blockIdx.x * blockDim.x + threadIdx.x;
    if (i >= n4) return;
    float4 v = in[i];
    o[2 * i]     = __floats2half2_rn(v.x, v.y);
    o[2 * i + 1] = __floats2half2_rn(v.z, v.w);
}

// per-expert transpose [R,C] -> [C,R] with fp32->fp16 conversion
__global__ void k_transpose_cvt(const float* __restrict__ in, __half* __restrict__ o,
                                int R, int C) {
    __shared__ float tile[32][33];
    size_t base = (size_t)blockIdx.z * R * C;
    int r0 = blockIdx.y * 32, c0 = blockIdx.x * 32;
    int tx = threadIdx.x, ty = threadIdx.y;
#pragma unroll
    for (int i = ty; i < 32; i += 8)
        tile[i][tx] = in[base + (size_t)(r0 + i) * C + c0 + tx];
    __syncthreads();
#pragma unroll
    for (int i = ty; i < 32; i += 8) {
        float v = tile[tx][i];
        size_t oo = base + (size_t)(c0 + i) * R + r0 + tx;
        o[oo] = __float2half_rn(v);
    }
}

// ---------------- grouped fp16 GEMM (single product, fp32 accum) ----------------
// CTA tile 256x128; 16 warps in 4(M)x4(N) grid of 64x32 warp tiles.
// A: [E*rowsA_pe, K] K-major fp16.  B: [E*rowsB_pe, K] K-major fp16.
// GELU_SPLIT: apply tanh-gelu, emit fp16 (GEMM1); else emit fp32 (GEMM2).
template <bool GELU_SPLIT>
__global__ void __launch_bounds__(NTHREADS, 1)
k_gemm(const __half* __restrict__ A, const __half* __restrict__ B,
       int K, int rowsA_pe, int rowsB_pe,
       __half* __restrict__ Oh, float* __restrict__ Of, int ldo) {
    extern __shared__ char smem[];
    uint32_t sb = smem_u32(smem);
    int tid = threadIdx.x, wid = tid >> 5, lid = tid & 31;

    size_t arow0 = (size_t)blockIdx.z * rowsA_pe + (size_t)blockIdx.y * MT;
    size_t brow0 = (size_t)blockIdx.z * rowsB_pe + (size_t)blockIdx.x * NT;
    size_t ncol0 = (size_t)blockIdx.x * NT;
    const int NC = K / KC;

    // warp tile: 64(M) x 32(N); mt 0..3 (m16), nt 0..3 (n8), np 0..1 (B n16 pairs)
    int m_off = (wid & 3) * 64;
    int n_off = (wid >> 2) * 32;
    uint32_t xorv = (uint32_t)(lid & 7) << 4;            // SW128 per-row XOR
    uint32_t a_row = (lid & 7) + ((lid >> 3) & 1) * 8;   // ldmatrix row-provider map
    uint32_t a_kx  = (uint32_t)(lid >> 4) * 16;          // k-byte half (0/16)
    uint32_t b_row = (lid & 7) + ((lid >> 4) & 1) * 8;
    uint32_t b_kx  = ((uint32_t)(lid >> 3) & 1) * 16;

    float acc[4][4][4];
#pragma unroll
    for (int mt = 0; mt < 4; ++mt)
#pragma unroll
        for (int nt = 0; nt < 4; ++nt)
#pragma unroll
            for (int r = 0; r < 4; ++r) acc[mt][nt][r] = 0.0f;

    // prologue: stages 0,1,2 in flight
    load_stage_async(sb, A, B, arow0, brow0, K, 0, tid);
    CP_COMMIT();
    load_stage_async(sb + STAGE_BYTES, A, B, arow0, brow0, K, KC, tid);
    CP_COMMIT();
    load_stage_async(sb + 2 * STAGE_BYTES, A, B, arow0, brow0, K, 2 * KC, tid);
    CP_COMMIT();

    for (int c = 0; c < NC; ++c) {
        CP_WAIT2();          // stage c landed (<=2 younger groups pending)
        __syncthreads();     // stage-c visible to all; buffer (c+3)%4 free (c-1 done)
        if (c + 3 < NC)
            load_stage_async(sb + ((c + 3) % NSTAGE) * STAGE_BYTES,
                             A, B, arow0, brow0, K, (size_t)(c + 3) * KC, tid);
        CP_COMMIT();         // commit every iter to keep group count stable

        uint32_t stg_u = sb + (c % NSTAGE) * STAGE_BYTES;
#pragma unroll
        for (int ks = 0; ks < KC / 16; ++ks) {
            uint32_t kin = (uint32_t)ks * 32;
            uint32_t av[4][4], bv[4][2];
#pragma unroll
            for (int mt = 0; mt < 4; ++mt) {
                uint32_t r = m_off + mt * 16 + a_row;
                uint32_t addr = stg_u + OFF_A + (r << 7) + ((kin + a_kx) ^ xorv);
                LDSM_X4(av[mt], addr);
            }
#pragma unroll
            for (int np = 0; np < 2; ++np) {
                uint32_t r = n_off + np * 16 + b_row;
                uint32_t addr = stg_u + OFF_B + (r << 7) + ((kin + b_kx) ^ xorv);
                uint32_t t0[4];
                LDSM_X4(t0, addr);
                bv[np * 2][0] = t0[0]; bv[np * 2][1] = t0[1];
                bv[np * 2 + 1][0] = t0[2]; bv[np * 2 + 1][1] = t0[3];
            }
#pragma unroll
            for (int mt = 0; mt < 4; ++mt)
#pragma unroll
                for (int nt = 0; nt < 4; ++nt)
                    mma16816(acc[mt][nt], av[mt], bv[nt]);
        }
    }

    // epilogue: thread holds D[g][2t..2t+1] (c0,c1) and D[g+8][2t..2t+1] (c2,c3)
    int g = lid >> 2, t2 = (lid & 3) * 2;
#pragma unroll
    for (int mt = 0; mt < 4; ++mt) {
#pragma unroll
        for (int nt = 0; nt < 4; ++nt) {
            size_t col = ncol0 + n_off + nt * 8 + t2;
            size_t row0 = arow0 + m_off + mt * 16 + g;
            size_t row1 = row0 + 8;
            float c0 = acc[mt][nt][0], c1 = acc[mt][nt][1];
            float c2 = acc[mt][nt][2], c3 = acc[mt][nt][3];
            if (GELU_SPLIT) {
                __half2 p0 = __floats2half2_rn(gelu_tanh(c0), gelu_tanh(c1));
                __half2 p1 = __floats2half2_rn(gelu_tanh(c2), gelu_tanh(c3));
                *(__half2*)(Oh + row0 * (size_t)ldo + col) = p0;
                *(__half2*)(Oh + row1 * (size_t)ldo + col) = p1;
            } else {
                *(float2*)(Of + row0 * (size_t)ldo + col) = make_float2(c0, c1);
                *(float2*)(Of + row1 * (size_t)ldo + col) = make_float2(c2, c3);
            }
        }
    }
}

// ---------------- launch ----------------
extern "C" void kernel_launch(void* const* d_in, const int* in_sizes, int n_in,
                              void* d_out, int out_size) {
    (void)in_sizes; (void)n_in; (void)out_size;
    const float* x  = (const float*)d_in[0];
    const float* w1 = (const float*)d_in[1];   // [E, H, F]
    const float* w2 = (const float*)d_in[2];   // [E, F, H]
    float* out = (float*)d_out;                // [T, H]

    __half *xq, *w1q, *w2q, *iq;
    cudaGetSymbolAddress((void**)&xq,  g_xq);
    cudaGetSymbolAddress((void**)&w1q, g_w1q);
    cudaGetSymbolAddress((void**)&w2q, g_w2q);
    cudaGetSymbolAddress((void**)&iq,  g_iq);

    // prep: convert x; transpose+convert weights to K-major B operands
    int n4 = T_ * H_ / 4;
    k_cvt<<<(n4 + 255) / 256, 256>>>((const float4*)x, (__half2*)xq, n4);
    dim3 tb(32, 8);
    k_transpose_cvt<<<dim3(F_ / 32, H_ / 32, E_), tb>>>(w1, w1q, H_, F_); // -> [E,F,H]
    k_transpose_cvt<<<dim3(H_ / 32, F_ / 32, E_), tb>>>(w2, w2q, F_, H_); // -> [E,H,F]

    cudaFuncSetAttribute(k_gemm<true>,  cudaFuncAttributeMaxDynamicSharedMemorySize, SMEM_TOTAL);
    cudaFuncSetAttribute(k_gemm<false>, cudaFuncAttributeMaxDynamicSharedMemorySize, SMEM_TOTAL);

    // GEMM1: I = gelu(X @ W1) -> fp16, [T, F]
    k_gemm<true><<<dim3(F_ / NT, TPE_ / MT, E_), NTHREADS, SMEM_TOTAL>>>(
        xq, w1q, H_, TPE_, F_, iq, nullptr, F_);
    // GEMM2: out = I @ W2 -> fp32, [T, H]
    k_gemm<false><<<dim3(H_ / NT, TPE_ / MT, E_), NTHREADS, SMEM_TOTAL>>>(
        iq, w2q, F_, TPE_, H_, nullptr, out, H_);
}